// round 16
// baseline (speedup 1.0000x reference)
#include <cuda_runtime.h>
#include <math.h>

#define CH     256
#define LEN    4096
#define HEADS  8
#define HDIM   32
#define B_MAX  8
#define NSPLIT 8

// ---------------- scratch (static device globals; no runtime allocation) ----
__device__ float g_q[B_MAX * CH * LEN];
__device__ float g_k[B_MAX * CH * LEN];
__device__ float g_v[B_MAX * CH * LEN];
__device__ float g_x[B_MAX * CH * LEN];
__device__ float g_kvp[NSPLIT * B_MAX * HEADS * 1056];   // per-split KV(1024)+ksum(32)
__device__ float g_kv[B_MAX * HEADS * HDIM * HDIM];
__device__ float g_ksum[B_MAX * HEADS * HDIM];

// ---------------- packed f32x2 helpers --------------------------------------
__device__ __forceinline__ void fma2(unsigned long long& d,
                                     unsigned long long a,
                                     unsigned long long b) {
    asm("fma.rn.f32x2 %0, %1, %2, %0;" : "+l"(d) : "l"(a), "l"(b));
}
__device__ __forceinline__ unsigned long long dup2(float x) {
    unsigned long long r;
    unsigned u = __float_as_uint(x);
    asm("mov.b64 %0, {%1, %1};" : "=l"(r) : "r"(u));
    return r;
}
__device__ __forceinline__ float f2lo(unsigned long long v) {
    return __uint_as_float((unsigned)v);
}
__device__ __forceinline__ float f2hi(unsigned long long v) {
    return __uint_as_float((unsigned)(v >> 32));
}

// ---------------- 256x4096 = W[256x256] * X[256x4096] GEMM ------------------
// BM=128, BN=128, BK=16, 256 threads, 8x8 per-thread, FFMA2 inner loop.
#define BM 128
#define BN 128
#define BK 16
#define KTILES (CH / BK)

// mode: 0/1 -> bias + (elu+1); 2 -> (bias + x) / L; 3 -> bias only
__device__ __forceinline__ void gemm_body(const float* __restrict__ W,
                                          const float* __restrict__ bias,
                                          const float* __restrict__ Bmat,
                                          float* __restrict__ C,
                                          int mode) {
    __shared__ float As[2][BK][BM + 4];
    __shared__ float Bs[2][BK][BN];

    const int tid = threadIdx.x;
    const int m0 = blockIdx.y * BM;
    const int n0 = blockIdx.x * BN;

    unsigned long long c2[8][4];
#pragma unroll
    for (int i = 0; i < 8; i++)
#pragma unroll
        for (int j = 0; j < 4; j++) c2[i][j] = 0ull;

    const int tm0 = (tid >> 4) << 3;
    const int tn0 = (tid & 15) << 3;

    float4 aval[2], bval[2];

    // prologue: tile 0 -> smem buf 0
#pragma unroll
    for (int i = 0; i < 2; i++) {
        int e = tid + i * 256;
        int m = e >> 2, kq = (e & 3) << 2;
        aval[i] = *(const float4*)(W + (m0 + m) * CH + kq);
        int rb = e >> 5, cb = (e & 31) << 2;
        bval[i] = *(const float4*)(Bmat + rb * LEN + n0 + cb);
    }
#pragma unroll
    for (int i = 0; i < 2; i++) {
        int e = tid + i * 256;
        int m = e >> 2, kq = (e & 3) << 2;
        As[0][kq + 0][m] = aval[i].x;
        As[0][kq + 1][m] = aval[i].y;
        As[0][kq + 2][m] = aval[i].z;
        As[0][kq + 3][m] = aval[i].w;
        int rb = e >> 5, cb = (e & 31) << 2;
        *(float4*)&Bs[0][rb][cb] = bval[i];
    }
    __syncthreads();

    int buf = 0;
    for (int kt = 0; kt < KTILES; kt++) {
        if (kt + 1 < KTILES) {
            int k0 = (kt + 1) * BK;
#pragma unroll
            for (int i = 0; i < 2; i++) {
                int e = tid + i * 256;
                int m = e >> 2, kq = (e & 3) << 2;
                aval[i] = *(const float4*)(W + (m0 + m) * CH + k0 + kq);
                int rb = e >> 5, cb = (e & 31) << 2;
                bval[i] = *(const float4*)(Bmat + (k0 + rb) * LEN + n0 + cb);
            }
        }
#pragma unroll
        for (int kk = 0; kk < BK; kk++) {
            float4 a0 = *(const float4*)&As[buf][kk][tm0];
            float4 a1 = *(const float4*)&As[buf][kk][tm0 + 4];
            const unsigned long long* bp =
                (const unsigned long long*)&Bs[buf][kk][tn0];
            unsigned long long b2[4];
            b2[0] = bp[0]; b2[1] = bp[1]; b2[2] = bp[2]; b2[3] = bp[3];
            float am[8] = {a0.x, a0.y, a0.z, a0.w, a1.x, a1.y, a1.z, a1.w};
#pragma unroll
            for (int m = 0; m < 8; m++) {
                unsigned long long ad = dup2(am[m]);
#pragma unroll
                for (int j = 0; j < 4; j++) fma2(c2[m][j], ad, b2[j]);
            }
        }
        if (kt + 1 < KTILES) {
            int nb = buf ^ 1;
#pragma unroll
            for (int i = 0; i < 2; i++) {
                int e = tid + i * 256;
                int m = e >> 2, kq = (e & 3) << 2;
                As[nb][kq + 0][m] = aval[i].x;
                As[nb][kq + 1][m] = aval[i].y;
                As[nb][kq + 2][m] = aval[i].z;
                As[nb][kq + 3][m] = aval[i].w;
                int rb = e >> 5, cb = (e & 31) << 2;
                *(float4*)&Bs[nb][rb][cb] = bval[i];
            }
        }
        __syncthreads();
        buf ^= 1;
    }

    const float invL = 1.0f / (float)LEN;
#pragma unroll
    for (int m = 0; m < 8; m++) {
        int o = m0 + tm0 + m;
        float bs = bias[o];
        float v[8];
#pragma unroll
        for (int j = 0; j < 4; j++) {
            v[2 * j + 0] = f2lo(c2[m][j]);
            v[2 * j + 1] = f2hi(c2[m][j]);
        }
#pragma unroll
        for (int j = 0; j < 8; j++) {
            float y = v[j] + bs;
            if (mode < 2)
                y = (y >= 0.f) ? (y + 1.f) : expf(y);   // elu(y)+1
            else if (mode == 2)
                y *= invL;
            v[j] = y;
        }
        float4* cp = (float4*)(C + (long)o * LEN + n0 + tn0);
        cp[0] = make_float4(v[0], v[1], v[2], v[3]);
        cp[1] = make_float4(v[4], v[5], v[6], v[7]);
    }
}

__global__ __launch_bounds__(256) void proj_gemm(
    const float* __restrict__ Xq, const float* __restrict__ Xk,
    const float* __restrict__ Xv, const float* __restrict__ Wq,
    const float* __restrict__ Wk, const float* __restrict__ Wv,
    const float* __restrict__ bq, const float* __restrict__ bk,
    const float* __restrict__ bv, int B) {
    int z = blockIdx.z;
    int p = z / B;
    int b = z - p * B;
    const float* X;
    const float* W;
    const float* bias;
    float* Y;
    if (p == 0)      { X = Xq; W = Wq; bias = bq; Y = g_q; }
    else if (p == 1) { X = Xk; W = Wk; bias = bk; Y = g_k; }
    else             { X = Xv; W = Wv; bias = bv; Y = g_v; }
    gemm_body(W, bias, X + (long)b * CH * LEN, Y + (long)b * CH * LEN, p);
}

__global__ __launch_bounds__(256) void final_gemm(
    const float* __restrict__ Wm, const float* __restrict__ bm,
    float* __restrict__ out) {
    int b = blockIdx.z;
    gemm_body(Wm, bm, g_x + (long)b * CH * LEN, out + (long)b * CH * LEN, 3);
}

// ---------------- KV / ksum (split over L) -----------------------------------
__global__ __launch_bounds__(256) void kv_partial() {
    const int s = blockIdx.x;   // L split
    const int h = blockIdx.y;   // head
    const int b = blockIdx.z;   // batch
    const int tid = threadIdx.x;

    __shared__ float kt[64][36];
    __shared__ float vt[64][36];

    float acc[4] = {0.f, 0.f, 0.f, 0.f};
    float ks = 0.f;

    const int q  = tid >> 3;          // 0..31 (v-dim)
    const int d0 = (tid & 7) << 2;    // 0..28 (k-dim group)

    const int lr = tid & 31;          // load: row d
    const int lc = (tid >> 5) << 3;   // load: col base (8 floats)

    const float* kbase = g_k + (long)b * CH * LEN;
    const float* vbase = g_v + (long)b * CH * LEN;
    const int l0s = s * (LEN / NSPLIT);

    for (int t = 0; t < (LEN / NSPLIT) / 64; t++) {
        int l0 = l0s + t * 64;
        long off = (long)(lr * 8 + h) * LEN + l0 + lc;
        float4 k4a = *(const float4*)(kbase + off);
        float4 k4b = *(const float4*)(kbase + off + 4);
        float4 v4a = *(const float4*)(vbase + off);
        float4 v4b = *(const float4*)(vbase + off + 4);
        __syncthreads();
        kt[lc + 0][lr] = k4a.x; kt[lc + 1][lr] = k4a.y;
        kt[lc + 2][lr] = k4a.z; kt[lc + 3][lr] = k4a.w;
        kt[lc + 4][lr] = k4b.x; kt[lc + 5][lr] = k4b.y;
        kt[lc + 6][lr] = k4b.z; kt[lc + 7][lr] = k4b.w;
        vt[lc + 0][lr] = v4a.x; vt[lc + 1][lr] = v4a.y;
        vt[lc + 2][lr] = v4a.z; vt[lc + 3][lr] = v4a.w;
        vt[lc + 4][lr] = v4b.x; vt[lc + 5][lr] = v4b.y;
        vt[lc + 6][lr] = v4b.z; vt[lc + 7][lr] = v4b.w;
        __syncthreads();
#pragma unroll 8
        for (int j = 0; j < 64; j++) {
            float vq = vt[j][q];
            float4 kd = *(const float4*)&kt[j][d0];
            acc[0] += kd.x * vq;
            acc[1] += kd.y * vq;
            acc[2] += kd.z * vq;
            acc[3] += kd.w * vq;
        }
        if (tid < 32) {
#pragma unroll 8
            for (int j = 0; j < 64; j++) ks += kt[j][tid];
        }
    }

    float* outp = g_kvp + ((long)((s * B_MAX + b) * HEADS + h)) * 1056;
    *(float4*)&outp[q * 32 + d0] = make_float4(acc[0], acc[1], acc[2], acc[3]);
    if (tid < 32) outp[1024 + tid] = ks;
}

__global__ __launch_bounds__(256) void kv_reduce() {
    const int bh = blockIdx.x;   // b*8+h
    const int tid = threadIdx.x;
    for (int e = tid; e < 1056; e += 256) {
        float s = 0.f;
#pragma unroll
        for (int sp = 0; sp < NSPLIT; sp++)
            s += g_kvp[((long)(sp * B_MAX * HEADS + bh)) * 1056 + e];
        if (e < 1024)
            g_kv[bh * 1024 + e] = s;
        else
            g_ksum[bh * 32 + (e - 1024)] = s;
    }
}

// ---------------- Z + readout: x[c,l] = L * Z[h,l] * sum_d q'[d,h,l]*KV[q,d,h]
#define XPITCH 68
__global__ __launch_bounds__(256) void attn_kernel() {
    extern __shared__ float sm[];
    float* qs  = sm;                       // [256][68] channel-major
    float* xs  = qs + 256 * XPITCH;        // [256][68]
    float* zs  = xs + 256 * XPITCH;        // [8][68]
    float* kss = zs + 8 * XPITCH;          // [256]

    const int tid = threadIdx.x;
    const int b = blockIdx.y;
    const int l0 = blockIdx.x * 64;

    kss[tid] = g_ksum[b * 256 + tid];

    const float* qg = g_q + (long)b * CH * LEN + l0;
#pragma unroll
    for (int i = 0; i < 16; i++) {
        int e = tid + (i << 8);
        int r = e >> 4;
        int c4 = (e & 15) << 2;
        *(float4*)&qs[r * XPITCH + c4] = *(const float4*)(qg + (long)r * LEN + c4);
    }
    __syncthreads();

    // Z[h,l] = L / (eps + sum_d q'[d*8+h, l] * ksum[h,d])
#pragma unroll
    for (int i = 0; i < 2; i++) {
        int p = tid + (i << 8);
        int hh = p >> 6, ll = p & 63;
        float s = 1e-6f;
#pragma unroll
        for (int d = 0; d < 32; d++)
            s += qs[((d << 3) + hh) * XPITCH + ll] * kss[(hh << 5) + d];
        zs[hh * XPITCH + ll] = (float)LEN / s;
    }

    // KV row for this thread's (q,h), pre-duplicated for f32x2
    const int qd = tid >> 3;
    const int h = tid & 7;
    unsigned long long kvd[32];
    {
        const float* kvp = g_kv + ((long)((b * 8 + h) * 32 + qd)) * 32;
#pragma unroll
        for (int d = 0; d < 32; d++) kvd[d] = dup2(kvp[d]);
    }
    __syncthreads();   // zs ready

#pragma unroll 4
    for (int l4 = 0; l4 < 64; l4 += 4) {
        unsigned long long accA = 0ull, accB = 0ull;
#pragma unroll
        for (int d = 0; d < 32; d++) {
            ulonglong2 qq =
                *(const ulonglong2*)&qs[((d << 3) + h) * XPITCH + l4];
            fma2(accA, kvd[d], qq.x);
            fma2(accB, kvd[d], qq.y);
        }
        float4 zq = *(const float4*)&zs[h * XPITCH + l4];
        float4 xv;
        xv.x = f2lo(accA) * zq.x;
        xv.y = f2hi(accA) * zq.y;
        xv.z = f2lo(accB) * zq.z;
        xv.w = f2hi(accB) * zq.w;
        *(float4*)&xs[tid * XPITCH + l4] = xv;
    }
    __syncthreads();

    float* xg = g_x + (long)b * CH * LEN + l0;
#pragma unroll
    for (int i = 0; i < 16; i++) {
        int e = tid + (i << 8);
        int r = e >> 4;
        int c4 = (e & 15) << 2;
        *(float4*)(xg + (long)r * LEN + c4) = *(const float4*)&xs[r * XPITCH + c4];
    }
}

// ---------------- launch -----------------------------------------------------
extern "C" void kernel_launch(void* const* d_in, const int* in_sizes, int n_in,
                              void* d_out, int out_size) {
    const float* query = (const float*)d_in[0];
    const float* key   = (const float*)d_in[1];
    const float* value = (const float*)d_in[2];
    const float* Wq = (const float*)d_in[3];
    const float* bq = (const float*)d_in[4];
    const float* Wk = (const float*)d_in[5];
    const float* bk = (const float*)d_in[6];
    const float* Wv = (const float*)d_in[7];
    const float* bv = (const float*)d_in[8];
    const float* Wm = (const float*)d_in[9];
    const float* bm = (const float*)d_in[10];
    float* out = (float*)d_out;

    int B = in_sizes[0] / (CH * LEN);
    if (B > B_MAX) B = B_MAX;

    dim3 blk(256);

    // 1) fused q/k/v projections (+ elu+1 / /L epilogues)
    dim3 g1(LEN / BN, CH / BM, 3 * B);
    proj_gemm<<<g1, blk>>>(query, key, value, Wq, Wk, Wv, bq, bk, bv, B);

    // 2) split-L KV + ksum, then reduce
    dim3 g2(NSPLIT, HEADS, B);
    kv_partial<<<g2, blk>>>();
    kv_reduce<<<B * HEADS, blk>>>();

    // 3) Z + attention readout -> g_x
    size_t smem3 = (size_t)(2 * 256 * XPITCH + 8 * XPITCH + 256) * sizeof(float);
    cudaFuncSetAttribute(attn_kernel, cudaFuncAttributeMaxDynamicSharedMemorySize,
                         (int)smem3);
    dim3 g3(LEN / 64, B);
    attn_kernel<<<g3, blk, smem3>>>();

    // 4) output projection
    dim3 g4(LEN / BN, CH / BM, B);
    final_gemm<<<g4, blk>>>(Wm, bm, out);
}